// round 1
// baseline (speedup 1.0000x reference)
#include <cuda_runtime.h>

// LIF neuron, T=4 unrolled. Layout [B, N, T] with T innermost -> float4 per neuron.
// thre = tanh(w); per step: reset = 1 - (o > thre); u = 0.25*u*reset + x + l;
// o = (u > thre) ? u : 0.

#define TAU 0.25f

__global__ __launch_bounds__(256) void lif_kernel(
    const float4* __restrict__ x,
    const float4* __restrict__ lat,
    const float* __restrict__ w,
    float4* __restrict__ out,
    int n)   // n = B*N neurons
{
    int i = blockIdx.x * blockDim.x + threadIdx.x;
    if (i >= n) return;

    const float thre = tanhf(w[0]);

    float4 xv = x[i];
    float4 lv = lat[i];
    float4 ov;

    // t = 0: u0 = 0, o0 = 0 -> reset irrelevant (TAU*0*reset = 0)
    float u = xv.x + lv.x;
    float o = (u > thre) ? u : 0.0f;
    ov.x = o;

    // t = 1
    float reset = (o > thre) ? 0.0f : 1.0f;
    u = TAU * u * reset + xv.y + lv.y;
    o = (u > thre) ? u : 0.0f;
    ov.y = o;

    // t = 2
    reset = (o > thre) ? 0.0f : 1.0f;
    u = TAU * u * reset + xv.z + lv.z;
    o = (u > thre) ? u : 0.0f;
    ov.z = o;

    // t = 3
    reset = (o > thre) ? 0.0f : 1.0f;
    u = TAU * u * reset + xv.w + lv.w;
    o = (u > thre) ? u : 0.0f;
    ov.w = o;

    out[i] = ov;
}

extern "C" void kernel_launch(void* const* d_in, const int* in_sizes, int n_in,
                              void* d_out, int out_size)
{
    const float4* x   = (const float4*)d_in[0];  // [B, N, T] float32
    const float4* lat = (const float4*)d_in[1];  // [B, N, T] float32
    const float*  w   = (const float*)d_in[2];   // scalar
    float4* out = (float4*)d_out;                // [B, N, T] float32

    int n = in_sizes[0] / 4;  // number of neurons (B*N); T=4 packed per float4
    int block = 256;
    int grid = (n + block - 1) / block;
    lif_kernel<<<grid, block>>>(x, lat, w, out, n);
}